// round 5
// baseline (speedup 1.0000x reference)
#include <cuda_runtime.h>
#include <cuda_bf16.h>
#include <cstdint>

// ============================================================================
// out = chain of 20 Linear(64,64) over x[524288,64], fp32.
// The chain is affine with no nonlinearity => compose the 20 maps into ONE
// (Mc, c): out = x @ Mc^T + c. Device-side tree composition (fp32 FFMA),
// then a single GEMM pass using mma.sync bf16x3 (base sm_103 target has no
// tcgen05 — ptxas rejects 'a'-suffix features in this build pipeline).
// ============================================================================

#define N_TOK   524288
#define DIM     64
#define LAYERS  20

// ---------------------------------------------------------------------------
// Affine-map buffers
// ---------------------------------------------------------------------------
struct AffineMap {
    float M[DIM * DIM];  // out_j = sum_k M[j][k] * in_k + c[j]
    float c[DIM];
};

__device__ AffineMap g_maps[2][LAYERS];

// ---------------------------------------------------------------------------
// Composition: generic pair compose over shared-memory tiles.
// dstM = Mb @ Ma ; dstc = Mb @ ca + cb   (A applied first).
// 256 threads, each computes a 4x4 block.
// ---------------------------------------------------------------------------
__device__ __forceinline__ void compose_body(
    const float* __restrict__ Ma, const float* __restrict__ ca,
    const float* __restrict__ Mb, const float* __restrict__ cb,
    float* __restrict__ dstM, float* __restrict__ dstc) {
    __shared__ float sMa[DIM * DIM];
    __shared__ float sMb[DIM * DIM];
    __shared__ float sca[DIM];

    for (int i = threadIdx.x; i < DIM * DIM; i += blockDim.x) {
        sMa[i] = Ma[i];
        sMb[i] = Mb[i];
    }
    if (threadIdx.x < DIM) sca[threadIdx.x] = ca[threadIdx.x];
    __syncthreads();

    int tx = threadIdx.x & 15;
    int ty = threadIdx.x >> 4;
    int j0 = ty * 4;
    int k0 = tx * 4;
    float acc[4][4] = {};
#pragma unroll 8
    for (int t = 0; t < DIM; t++) {
        float4 av = *reinterpret_cast<const float4*>(&sMa[t * DIM + k0]);
        float b0 = sMb[(j0 + 0) * DIM + t];
        float b1 = sMb[(j0 + 1) * DIM + t];
        float b2 = sMb[(j0 + 2) * DIM + t];
        float b3 = sMb[(j0 + 3) * DIM + t];
        acc[0][0] += b0 * av.x; acc[0][1] += b0 * av.y; acc[0][2] += b0 * av.z; acc[0][3] += b0 * av.w;
        acc[1][0] += b1 * av.x; acc[1][1] += b1 * av.y; acc[1][2] += b1 * av.z; acc[1][3] += b1 * av.w;
        acc[2][0] += b2 * av.x; acc[2][1] += b2 * av.y; acc[2][2] += b2 * av.z; acc[2][3] += b2 * av.w;
        acc[3][0] += b3 * av.x; acc[3][1] += b3 * av.y; acc[3][2] += b3 * av.z; acc[3][3] += b3 * av.w;
    }
#pragma unroll
    for (int jj = 0; jj < 4; jj++)
#pragma unroll
        for (int kk = 0; kk < 4; kk++)
            dstM[(j0 + jj) * DIM + (k0 + kk)] = acc[jj][kk];

    if (threadIdx.x < DIM) {
        int j = threadIdx.x;
        float s = cb[j];
#pragma unroll 8
        for (int t = 0; t < DIM; t++) s += sMb[j * DIM + t] * sca[t];
        dstc[j] = s;
    }
}

// Level 0: read raw weights W[L][out][in], b[L][out]; compose pairs
// (layer 2i then 2i+1) directly into g_maps[1][i].  10 CTAs.
__global__ void compose_lvl0_kernel(const float* __restrict__ W,
                                    const float* __restrict__ b) {
    int i = blockIdx.x;
    compose_body(W + (2 * i) * DIM * DIM, b + (2 * i) * DIM,
                 W + (2 * i + 1) * DIM * DIM, b + (2 * i + 1) * DIM,
                 g_maps[0][i].M, g_maps[0][i].c);
}

// Higher levels: compose adjacent pairs from g_maps[src] -> g_maps[src^1].
__global__ void compose_pair_kernel(int src, int n_in) {
    int i0 = 2 * blockIdx.x;
    int i1 = i0 + 1;
    AffineMap* dst = &g_maps[src ^ 1][blockIdx.x];

    if (i1 >= n_in) {  // odd leftover: plain copy
        const AffineMap* s = &g_maps[src][i0];
        for (int i = threadIdx.x; i < DIM * DIM; i += blockDim.x)
            dst->M[i] = s->M[i];
        if (threadIdx.x < DIM) dst->c[threadIdx.x] = s->c[threadIdx.x];
        return;
    }
    const AffineMap* A = &g_maps[src][i0];
    const AffineMap* B = &g_maps[src][i1];
    compose_body(A->M, A->c, B->M, B->c, dst->M, dst->c);
}

// ---------------------------------------------------------------------------
// Apply: out = x @ Mc^T + c via mma.sync m16n8k16 bf16, error-free-ish
// bf16x3 split (AhiBhi + AhiBlo + AloBhi), fp32 accumulate.
//
// CTA = 256 threads = 8 warps. Warp (w>>1, w&1) computes a 16-row x 32-col
// block; CTA covers 64 rows x 64 cols. Grid = N_TOK/64 = 8192 CTAs.
// Fragments load straight from global memory:
//   A m16n8k16 frag: per-thread float2 pairs of x (rows g/g+8, k-pairs)
//   B frag: per-thread float2 pairs of Mc[n][k] (k contiguous) — L2 resident.
// ---------------------------------------------------------------------------
__device__ __forceinline__ void split2(float2 v, uint32_t& hi, uint32_t& lo) {
    __nv_bfloat16 hx = __float2bfloat16_rn(v.x);
    __nv_bfloat16 hy = __float2bfloat16_rn(v.y);
    __nv_bfloat16 lx = __float2bfloat16_rn(v.x - __bfloat162float(hx));
    __nv_bfloat16 ly = __float2bfloat16_rn(v.y - __bfloat162float(hy));
    hi = (uint32_t)__bfloat16_as_ushort(hx) |
         ((uint32_t)__bfloat16_as_ushort(hy) << 16);
    lo = (uint32_t)__bfloat16_as_ushort(lx) |
         ((uint32_t)__bfloat16_as_ushort(ly) << 16);
}

__device__ __forceinline__ void mma16816(float* c, const uint32_t* a,
                                         const uint32_t* b) {
    asm volatile(
        "mma.sync.aligned.m16n8k16.row.col.f32.bf16.bf16.f32 "
        "{%0,%1,%2,%3}, {%4,%5,%6,%7}, {%8,%9}, {%0,%1,%2,%3};\n"
        : "+f"(c[0]), "+f"(c[1]), "+f"(c[2]), "+f"(c[3])
        : "r"(a[0]), "r"(a[1]), "r"(a[2]), "r"(a[3]), "r"(b[0]), "r"(b[1]));
}

__global__ void __launch_bounds__(256)
apply_kernel(const float* __restrict__ x, float* __restrict__ out) {
    const int tid  = threadIdx.x;
    const int lane = tid & 31;
    const int w    = tid >> 5;
    const int g    = lane >> 2;   // 0..7  (row/col group)
    const int tig  = lane & 3;    // 0..3

    const int warp_r = (w >> 1) * 16;      // 0,16,32,48
    const int warp_c = (w & 1) * 32;       // 0,32

    const float* __restrict__ Mc = g_maps[1][0].M;
    const float* __restrict__ cc = g_maps[1][0].c;

    // ---- B fragments (composite matrix), bf16x3 split, held in regs ----
    uint32_t bhi[4][4][2], blo[4][4][2];   // [kt][nt][reg]
#pragma unroll
    for (int kt = 0; kt < 4; kt++)
#pragma unroll
        for (int nt = 0; nt < 4; nt++) {
            int n = warp_c + nt * 8 + g;
            const float* br = Mc + n * DIM + kt * 16 + 2 * tig;
            float2 p0 = *reinterpret_cast<const float2*>(br);
            float2 p1 = *reinterpret_cast<const float2*>(br + 8);
            split2(p0, bhi[kt][nt][0], blo[kt][nt][0]);
            split2(p1, bhi[kt][nt][1], blo[kt][nt][1]);
        }

    // ---- bias fragments ----
    float2 bias[4];
#pragma unroll
    for (int nt = 0; nt < 4; nt++) {
        int col = warp_c + nt * 8 + 2 * tig;
        bias[nt] = *reinterpret_cast<const float2*>(cc + col);
    }

    // ---- A fragments + MMA ----
    const size_t r0 = (size_t)blockIdx.x * 64 + warp_r + g;
    const float* __restrict__ xr = x + r0 * DIM;

    float acc[4][4] = {};
#pragma unroll
    for (int kt = 0; kt < 4; kt++) {
        int kk = kt * 16 + 2 * tig;
        float2 a00 = *reinterpret_cast<const float2*>(xr + kk);
        float2 a10 = *reinterpret_cast<const float2*>(xr + 8 * DIM + kk);
        float2 a01 = *reinterpret_cast<const float2*>(xr + kk + 8);
        float2 a11 = *reinterpret_cast<const float2*>(xr + 8 * DIM + kk + 8);
        uint32_t ahi[4], alo[4];
        split2(a00, ahi[0], alo[0]);
        split2(a10, ahi[1], alo[1]);
        split2(a01, ahi[2], alo[2]);
        split2(a11, ahi[3], alo[3]);
#pragma unroll
        for (int nt = 0; nt < 4; nt++) {
            mma16816(acc[nt], ahi, bhi[kt][nt]);
            mma16816(acc[nt], ahi, blo[kt][nt]);
            mma16816(acc[nt], alo, bhi[kt][nt]);
        }
    }

    // ---- Epilogue: add bias, store float2 pairs ----
    float* __restrict__ orow = out + r0 * DIM;
#pragma unroll
    for (int nt = 0; nt < 4; nt++) {
        int col = warp_c + nt * 8 + 2 * tig;
        float2 v0 = make_float2(acc[nt][0] + bias[nt].x, acc[nt][1] + bias[nt].y);
        float2 v1 = make_float2(acc[nt][2] + bias[nt].x, acc[nt][3] + bias[nt].y);
        *reinterpret_cast<float2*>(orow + col) = v0;
        *reinterpret_cast<float2*>(orow + 8 * DIM + col) = v1;
    }
}

// ---------------------------------------------------------------------------
// Launch
// ---------------------------------------------------------------------------
extern "C" void kernel_launch(void* const* d_in, const int* in_sizes, int n_in,
                              void* d_out, int out_size) {
    const float* x = (const float*)d_in[0];  // [524288, 64]
    const float* W = (const float*)d_in[1];  // [20, 64, 64]
    const float* b = (const float*)d_in[2];  // [20, 64]
    float* out = (float*)d_out;              // [524288, 64]

    // Tree compose: 20 -> 10 (from raw weights, into buf0) -> 5 -> 3 -> 2 -> 1
    compose_lvl0_kernel<<<10, 256>>>(W, b);  // -> g_maps[0][0..9]
    compose_pair_kernel<<<5, 256>>>(0, 10);  // -> buf1 (5)
    compose_pair_kernel<<<3, 256>>>(1, 5);   // -> buf0 (3)
    compose_pair_kernel<<<2, 256>>>(0, 3);   // -> buf1 (2)
    compose_pair_kernel<<<1, 256>>>(1, 2);   // -> buf0 (1)
    // One more hop so the final map lands in g_maps[1][0] (apply reads there).
    compose_pair_kernel<<<1, 256>>>(0, 1);   // copy buf0[0] -> buf1[0]

    apply_kernel<<<N_TOK / 64, 256>>>(x, out);
}